// round 9
// baseline (speedup 1.0000x reference)
#include <cuda_runtime.h>
#include <math.h>

// Problem dims
#define S_ 2048
#define B_ 64
#define I_ 256
#define H_ 512
#define ROWS_ (S_ * B_)          // 131072
#define BH_ (B_ * H_)

// ---------------- scratch (no cudaMalloc allowed) ----------------
__device__ float g_buf0[(size_t)S_ * BH_];   // xb0 from projection

// ---------------- packed f32x2 FMA ----------------
__device__ __forceinline__ void fma2(float2& d, float ax, float ay,
                                     float bx, float by) {
    asm volatile(
        "{\n\t"
        ".reg .b64 ra, rb, rd;\n\t"
        "mov.b64 ra, {%2, %3};\n\t"
        "mov.b64 rb, {%4, %5};\n\t"
        "mov.b64 rd, {%0, %1};\n\t"
        "fma.rn.f32x2 rd, ra, rb, rd;\n\t"
        "mov.b64 {%0, %1}, rd;\n\t"
        "}"
        : "+f"(d.x), "+f"(d.y)
        : "f"(ax), "f"(ay), "f"(bx), "f"(by));
}

__device__ __forceinline__ unsigned su32(const void* p) {
    return (unsigned)__cvta_generic_to_shared(p);
}

// ---------------- projection GEMM (layer 0 only) ----------------
#define TM 64
#define TN 64
#define KC 64
#define SAST 66

__global__ void __launch_bounds__(256) proj_kernel(
    const float* __restrict__ A,
    const float* __restrict__ W,
    const int*   __restrict__ Wmask,
    const float* __restrict__ bias1,
    const float* __restrict__ bias2,
    int K)
{
    __shared__ float SA[TM * SAST];
    __shared__ float SW[TN * SAST];

    float* C = g_buf0;
    const int m0 = blockIdx.x * TM;
    const int n0 = blockIdx.y * TN;
    const int tid = threadIdx.x;
    const int tx = tid & 15;
    const int ty = tid >> 4;

    float2 acc[4][4];
#pragma unroll
    for (int i = 0; i < 4; i++)
#pragma unroll
        for (int j = 0; j < 4; j++) acc[i][j] = make_float2(0.f, 0.f);

    for (int kc = 0; kc < K; kc += KC) {
#pragma unroll
        for (int t = tid; t < TM * 16; t += 256) {
            int r = t >> 4, q = t & 15;
            float4 v = *(const float4*)&A[(size_t)(m0 + r) * K + kc + 4 * q];
            int o = r * SAST + 4 * q;
            *(float2*)&SA[o]     = make_float2(v.x, v.y);
            *(float2*)&SA[o + 2] = make_float2(v.z, v.w);
        }
#pragma unroll
        for (int t = tid; t < TN * 16; t += 256) {
            int r = t >> 4, q = t & 15;
            size_t g = (size_t)(n0 + r) * K + kc + 4 * q;
            float4 v = *(const float4*)&W[g];
            int4  mm = *(const int4*)&Wmask[g];
            int o = r * SAST + 4 * q;
            SW[o]     = v.x * (float)mm.x;
            SW[o + 1] = v.y * (float)mm.y;
            SW[o + 2] = v.z * (float)mm.z;
            SW[o + 3] = v.w * (float)mm.w;
        }
        __syncthreads();

#pragma unroll 8
        for (int k = 0; k < KC; k += 2) {
            float2 a[4], w[4];
#pragma unroll
            for (int i = 0; i < 4; i++) a[i] = *(float2*)&SA[(ty + 16 * i) * SAST + k];
#pragma unroll
            for (int j = 0; j < 4; j++) w[j] = *(float2*)&SW[(tx + 16 * j) * SAST + k];
#pragma unroll
            for (int i = 0; i < 4; i++)
#pragma unroll
                for (int j = 0; j < 4; j++)
                    fma2(acc[i][j], a[i].x, a[i].y, w[j].x, w[j].y);
        }
        __syncthreads();
    }

#pragma unroll
    for (int j = 0; j < 4; j++) {
        int n = n0 + tx + 16 * j;
        float bb = bias1[n] + bias2[n];
#pragma unroll
        for (int i = 0; i < 4; i++) {
            int m = m0 + ty + 16 * i;
            C[(size_t)m * H_ + n] = acc[i][j].x + acc[i][j].y + bb;
        }
    }
}

// ---------------- cluster recurrence kernel -------------------------------
// 8 clusters of 16 CTAs. Cluster = batch-group (8 rows x full 512 cols).
// CTA = 8 rows x 32 cols, 256 threads: col = tid&31, ks = tid>>5 (8 x 64-k).
// Exchange: st.async (y0[t], y1[t-1]) pairs to all 16 CTAs' double-buffered
// recv buffer; sync via local smem mbarrier expect_tx. No global traffic for
// h at all; xb0 prefetched from g_buf0; y1[S-1] written straight to d_out.
#define NCTA 128
#define CLSZ 16
#define RTH  256
#define BROWS 8
#define BCOLS 32
// smem layout (floats)
#define BUF_OFF   0            // [2][4096 pairs] = 16384 floats (64 KB)
#define RED01_OFF 16384        // [8][256] float2 = 4096 floats
#define RED2_OFF  20480        // [8][256] float  = 2048 floats
#define MBAR_OFF  22528        // byte 90112: 2 x u64 mbarriers
#define SMEM_FLOATS 22532
#define RNN_SMEM_BYTES (SMEM_FLOATS * 4)   // 90128 B
#define TX_BYTES 32768u        // 4096 pairs * 8B per step

__device__ __forceinline__ void bar_wait_cluster(unsigned addr, unsigned parity) {
    unsigned done;
    asm volatile(
        "{\n\t"
        ".reg .pred p;\n\t"
        "mbarrier.try_wait.parity.acquire.cluster.shared::cta.b64 p, [%1], %2;\n\t"
        "selp.b32 %0, 1, 0, p;\n\t"
        "}"
        : "=r"(done) : "r"(addr), "r"(parity) : "memory");
    if (!done) {
        asm volatile(
            "{\n\t"
            ".reg .pred P1;\n\t"
            "WAIT_LOOP_%=:\n\t"
            "mbarrier.try_wait.parity.acquire.cluster.shared::cta.b64 P1, [%0], %1, 0x989680;\n\t"
            "@P1 bra.uni WAIT_DONE_%=;\n\t"
            "bra.uni WAIT_LOOP_%=;\n\t"
            "WAIT_DONE_%=:\n\t"
            "}"
            :: "r"(addr), "r"(parity) : "memory");
    }
}

__global__ void __launch_bounds__(RTH, 1) rnn_cluster_kernel(
    const float* __restrict__ Whh0, const int* __restrict__ m_hh0,
    const float* __restrict__ Wih1, const int* __restrict__ m_ih1,
    const float* __restrict__ Whh1, const int* __restrict__ m_hh1,
    const float* __restrict__ b_ih1, const float* __restrict__ b_hh1,
    float* __restrict__ out)
{
    extern __shared__ float smem[];
    float* red01 = smem + RED01_OFF;
    float* red2  = smem + RED2_OFF;
    const unsigned smem_base = su32(smem);
    const unsigned bar_base  = smem_base + MBAR_OFF * 4u;

    const int bg  = blockIdx.x >> 4;   // 0..7  batch-group == cluster
    const int hg  = blockIdx.x & 15;   // 0..15 == cluster rank
    const int b0  = bg * BROWS;
    const int h0  = hg * BCOLS;
    const int tid = threadIdx.x;
    const int col = tid & 31;          // output col this thread accumulates for
    const int ks  = tid >> 5;          // 0..7, 64-k slice
    const int k0  = ks * 64;

    if (tid == 0) {
        asm volatile("mbarrier.init.shared.b64 [%0], 1;" :: "r"(bar_base) : "memory");
        asm volatile("mbarrier.init.shared.b64 [%0], 1;" :: "r"(bar_base + 8) : "memory");
    }

    // ---- permanent register weights: 16 float4 per gemm (64 k) ----
    float4 wr0[16], wr1[16], wr2[16];
    {
        size_t ro = (size_t)(h0 + col) * H_ + k0;
#pragma unroll
        for (int q = 0; q < 16; q++) {
            float4 v; int4 mm;
            v = *(const float4*)&Whh0[ro + 4 * q];
            mm = *(const int4*)&m_hh0[ro + 4 * q];
            wr0[q] = make_float4(v.x * (float)mm.x, v.y * (float)mm.y,
                                 v.z * (float)mm.z, v.w * (float)mm.w);
            v = *(const float4*)&Wih1[ro + 4 * q];
            mm = *(const int4*)&m_ih1[ro + 4 * q];
            wr1[q] = make_float4(v.x * (float)mm.x, v.y * (float)mm.y,
                                 v.z * (float)mm.z, v.w * (float)mm.w);
            v = *(const float4*)&Whh1[ro + 4 * q];
            mm = *(const int4*)&m_hh1[ro + 4 * q];
            wr2[q] = make_float4(v.x * (float)mm.x, v.y * (float)mm.y,
                                 v.z * (float)mm.z, v.w * (float)mm.w);
        }
    }
    __syncthreads();
    // mbarriers must be visible cluster-wide before any st.async targets them
    asm volatile("barrier.cluster.arrive.aligned;" ::: "memory");
    asm volatile("barrier.cluster.wait.aligned;" ::: "memory");

    // output mapping: thread -> (row tid>>5, col tid&31) of its 8x32 tile
    const int orow = tid >> 5;
    const int ocol = tid & 31;
    const size_t offO = (size_t)(b0 + orow) * H_ + (h0 + ocol);
    const float bL1 = __ldg(&b_ih1[h0 + ocol]) + __ldg(&b_hh1[h0 + ocol]);
    float xv = __ldg(&g_buf0[offO]);

    // my send slot (same offset in every CTA's recv buffer): pair index hg*256+tid
    const unsigned slot_rel = (unsigned)((hg * 256 + tid) * 8);

    for (int t = 0; t <= S_; ++t) {
        float s0 = 0.f, s1 = 0.f, s2 = 0.f;

        if (t > 0) {
            const int pb = (t - 1) & 1;
            bar_wait_cluster(bar_base + pb * 8, (unsigned)(((t - 1) >> 1) & 1));

            const float* bp = smem + BUF_OFF + pb * 8192;   // pairs as floats
            // gemm: for each row, slices 2ks (cols k0..k0+31) and 2ks+1
#pragma unroll 2
            for (int r = 0; r < BROWS; r++) {
                const float4* apA = (const float4*)(bp + ((2 * ks) * 256 + r * 32) * 2);
                const float4* apB = (const float4*)(bp + ((2 * ks + 1) * 256 + r * 32) * 2);
                float2 u0 = make_float2(0.f, 0.f);
                float2 u1 = make_float2(0.f, 0.f);
                float2 u2 = make_float2(0.f, 0.f);
#pragma unroll
                for (int q = 0; q < 8; q++) {
                    float4 d0 = apA[2 * q];       // cols 4q, 4q+1: (y0,y1,y0,y1)
                    float4 d1 = apA[2 * q + 1];   // cols 4q+2, 4q+3
                    float4 w0 = wr0[q], w1 = wr1[q], w2 = wr2[q];
                    fma2(u0, d0.x, d0.z, w0.x, w0.y);
                    fma2(u0, d1.x, d1.z, w0.z, w0.w);
                    fma2(u1, d0.x, d0.z, w1.x, w1.y);
                    fma2(u1, d1.x, d1.z, w1.z, w1.w);
                    fma2(u2, d0.y, d0.w, w2.x, w2.y);
                    fma2(u2, d1.y, d1.w, w2.z, w2.w);
                }
#pragma unroll
                for (int q = 0; q < 8; q++) {
                    float4 d0 = apB[2 * q];
                    float4 d1 = apB[2 * q + 1];
                    float4 w0 = wr0[8 + q], w1 = wr1[8 + q], w2 = wr2[8 + q];
                    fma2(u0, d0.x, d0.z, w0.x, w0.y);
                    fma2(u0, d1.x, d1.z, w0.z, w0.w);
                    fma2(u1, d0.x, d0.z, w1.x, w1.y);
                    fma2(u1, d1.x, d1.z, w1.z, w1.w);
                    fma2(u2, d0.y, d0.w, w2.x, w2.y);
                    fma2(u2, d1.y, d1.w, w2.z, w2.w);
                }
                *(float2*)&red01[(ks * 256 + r * 32 + col) * 2] =
                    make_float2(u0.x + u0.y, u1.x + u1.y);
                red2[ks * 256 + r * 32 + col] = u2.x + u2.y;
            }
            __syncthreads();

#pragma unroll
            for (int k = 0; k < 8; k++) {
                float2 v = *(const float2*)&red01[(k * 256 + tid) * 2];
                s0 += v.x;
                s1 += v.y;
                s2 += red2[k * 256 + tid];
            }
        }

        float y0v = 0.f, y1v = 0.f;
        if (t < S_) y0v = tanhf(s0 + xv);
        if (t > 0)  y1v = tanhf(s1 + s2 + bL1);

        if (t == S_) {
            out[offO] = y1v;           // final y1[S-1] straight to output
        } else {
            const int sb = t & 1;
            if (tid == 0) {
                asm volatile(
                    "mbarrier.arrive.expect_tx.shared.b64 _, [%0], %1;"
                    :: "r"(bar_base + sb * 8), "r"(TX_BYTES) : "memory");
            }
            unsigned long long pv;
            asm("mov.b64 %0, {%1, %2};" : "=l"(pv) : "f"(y0v), "f"(y1v));
            const unsigned lslot = smem_base + (unsigned)(BUF_OFF * 4)
                                 + (unsigned)(sb * 8192 * 4) + slot_rel;
            const unsigned lbar  = bar_base + sb * 8;
#pragma unroll
            for (int c = 0; c < CLSZ; c++) {
                unsigned rslot, rbar;
                asm("mapa.shared::cluster.u32 %0, %1, %2;"
                    : "=r"(rslot) : "r"(lslot), "r"(c));
                asm("mapa.shared::cluster.u32 %0, %1, %2;"
                    : "=r"(rbar) : "r"(lbar), "r"(c));
                asm volatile(
                    "st.async.shared::cluster.mbarrier::complete_tx::bytes.b64 [%0], %1, [%2];"
                    :: "r"(rslot), "l"(pv), "r"(rbar) : "memory");
            }
            if (t + 1 < S_)
                xv = __ldg(&g_buf0[(size_t)(t + 1) * BH_ + offO]);
        }
    }

    // keep cluster resident until everyone's in-flight st.async has landed
    asm volatile("barrier.cluster.arrive.aligned;" ::: "memory");
    asm volatile("barrier.cluster.wait.aligned;" ::: "memory");
}

// ---------------- launch ----------------
extern "C" void kernel_launch(void* const* d_in, const int* in_sizes, int n_in,
                              void* d_out, int out_size) {
    const float* x       = (const float*)d_in[0];
    const float* W_ih0   = (const float*)d_in[1];
    const float* W_hh0   = (const float*)d_in[2];
    const float* b_ih0   = (const float*)d_in[3];
    const float* b_hh0   = (const float*)d_in[4];
    const float* W_ih1   = (const float*)d_in[5];
    const float* W_hh1   = (const float*)d_in[6];
    const float* b_ih1   = (const float*)d_in[7];
    const float* b_hh1   = (const float*)d_in[8];
    const int*   m_ih0   = (const int*)d_in[9];
    const int*   m_hh0   = (const int*)d_in[10];
    const int*   m_ih1   = (const int*)d_in[11];
    const int*   m_hh1   = (const int*)d_in[12];
    float* out = (float*)d_out;

    static bool attr_set = false;
    if (!attr_set) {
        cudaFuncSetAttribute(rnn_cluster_kernel,
                             cudaFuncAttributeMaxDynamicSharedMemorySize,
                             RNN_SMEM_BYTES);
        cudaFuncSetAttribute(rnn_cluster_kernel,
                             cudaFuncAttributeNonPortableClusterSizeAllowed, 1);
        attr_set = true;
    }

    // layer-0 input projection: xb0 = x @ (Wih0*m)^T + b_ih0 + b_hh0 -> g_buf0
    dim3 pgrid(ROWS_ / TM, H_ / TN);
    proj_kernel<<<pgrid, 256>>>(x, W_ih0, m_ih0, b_ih0, b_hh0, I_);

    // fused 2-layer recurrence across 8 x 16-CTA clusters
    cudaLaunchConfig_t cfg = {};
    cfg.gridDim  = dim3(NCTA, 1, 1);
    cfg.blockDim = dim3(RTH, 1, 1);
    cfg.dynamicSmemBytes = RNN_SMEM_BYTES;
    cfg.stream = 0;
    cudaLaunchAttribute at[1];
    at[0].id = cudaLaunchAttributeClusterDimension;
    at[0].val.clusterDim.x = CLSZ;
    at[0].val.clusterDim.y = 1;
    at[0].val.clusterDim.z = 1;
    cfg.attrs = at;
    cfg.numAttrs = 1;
    cudaLaunchKernelEx(&cfg, rnn_cluster_kernel,
                       W_hh0, m_hh0, W_ih1, m_ih1, W_hh1, m_hh1,
                       b_ih1, b_hh1, out);
}

// round 10
// speedup vs baseline: 1.7337x; 1.7337x over previous
#include <cuda_runtime.h>
#include <math.h>

// Problem dims
#define S_ 2048
#define B_ 64
#define I_ 256
#define H_ 512
#define ROWS_ (S_ * B_)          // 131072
#define BH_ (B_ * H_)

// ---------------- scratch (no cudaMalloc allowed) ----------------
__device__ float g_buf0[(size_t)S_ * BH_];       // xb0 from projection
__device__ float2 g_pack[2][B_][H_];             // (y0,y1) exchange ring (512KB, L2)
__device__ unsigned g_ctr[256];                  // per-bgroup arrival counter @ bg*32

// ---------------- packed f32x2 FMA ----------------
__device__ __forceinline__ void fma2(float2& d, float ax, float ay,
                                     float bx, float by) {
    asm volatile(
        "{\n\t"
        ".reg .b64 ra, rb, rd;\n\t"
        "mov.b64 ra, {%2, %3};\n\t"
        "mov.b64 rb, {%4, %5};\n\t"
        "mov.b64 rd, {%0, %1};\n\t"
        "fma.rn.f32x2 rd, ra, rb, rd;\n\t"
        "mov.b64 {%0, %1}, rd;\n\t"
        "}"
        : "+f"(d.x), "+f"(d.y)
        : "f"(ax), "f"(ay), "f"(bx), "f"(by));
}

__device__ __forceinline__ unsigned su32(const void* p) {
    return (unsigned)__cvta_generic_to_shared(p);
}
__device__ __forceinline__ void cp16(unsigned dst, const void* src) {
    asm volatile("cp.async.cg.shared.global [%0], [%1], 16;" :: "r"(dst), "l"(src));
}
#define CP_COMMIT() asm volatile("cp.async.commit_group;" ::: "memory")
#define CP_WAIT0()  asm volatile("cp.async.wait_group 0;" ::: "memory")

// ---------------- counter init (graph-replay safe reset) ----------------
__global__ void init_ctrs_kernel() {
    g_ctr[threadIdx.x] = 0u;
}

// ---------------- projection GEMM (layer 0 only) ----------------
#define TM 64
#define TN 64
#define KC 64
#define SAST 66

__global__ void __launch_bounds__(256) proj_kernel(
    const float* __restrict__ A,
    const float* __restrict__ W,
    const int*   __restrict__ Wmask,
    const float* __restrict__ bias1,
    const float* __restrict__ bias2,
    int K)
{
    __shared__ float SA[TM * SAST];
    __shared__ float SW[TN * SAST];

    float* C = g_buf0;
    const int m0 = blockIdx.x * TM;
    const int n0 = blockIdx.y * TN;
    const int tid = threadIdx.x;
    const int tx = tid & 15;
    const int ty = tid >> 4;

    float2 acc[4][4];
#pragma unroll
    for (int i = 0; i < 4; i++)
#pragma unroll
        for (int j = 0; j < 4; j++) acc[i][j] = make_float2(0.f, 0.f);

    for (int kc = 0; kc < K; kc += KC) {
#pragma unroll
        for (int t = tid; t < TM * 16; t += 256) {
            int r = t >> 4, q = t & 15;
            float4 v = *(const float4*)&A[(size_t)(m0 + r) * K + kc + 4 * q];
            int o = r * SAST + 4 * q;
            *(float2*)&SA[o]     = make_float2(v.x, v.y);
            *(float2*)&SA[o + 2] = make_float2(v.z, v.w);
        }
#pragma unroll
        for (int t = tid; t < TN * 16; t += 256) {
            int r = t >> 4, q = t & 15;
            size_t g = (size_t)(n0 + r) * K + kc + 4 * q;
            float4 v = *(const float4*)&W[g];
            int4  mm = *(const int4*)&Wmask[g];
            int o = r * SAST + 4 * q;
            SW[o]     = v.x * (float)mm.x;
            SW[o + 1] = v.y * (float)mm.y;
            SW[o + 2] = v.z * (float)mm.z;
            SW[o + 3] = v.w * (float)mm.w;
        }
        __syncthreads();

#pragma unroll 8
        for (int k = 0; k < KC; k += 2) {
            float2 a[4], w[4];
#pragma unroll
            for (int i = 0; i < 4; i++) a[i] = *(float2*)&SA[(ty + 16 * i) * SAST + k];
#pragma unroll
            for (int j = 0; j < 4; j++) w[j] = *(float2*)&SW[(tx + 16 * j) * SAST + k];
#pragma unroll
            for (int i = 0; i < 4; i++)
#pragma unroll
                for (int j = 0; j < 4; j++)
                    fma2(acc[i][j], a[i].x, a[i].y, w[j].x, w[j].y);
        }
        __syncthreads();
    }

#pragma unroll
    for (int j = 0; j < 4; j++) {
        int n = n0 + tx + 16 * j;
        float bb = bias1[n] + bias2[n];
#pragma unroll
        for (int i = 0; i < 4; i++) {
            int m = m0 + ty + 16 * i;
            C[(size_t)m * H_ + n] = acc[i][j].x + acc[i][j].y + bb;
        }
    }
}

// ---------------- fused 2-layer recurrence (R8 skeleton, packed ring) -----
// round t: L0 computes y0[t] (t<S), L1 computes y1[t-1] (t>=1).
// 128 CTAs = 8 bg x 16 hg; CTA = 8 rows x 32 cols; 256 threads:
// col = tid&31, ks = tid>>5 (8 x 64-k slices); weights (3x64) in registers.
// Exchange: g_pack ring of 2 steps holding (y0,y1) pairs; sync = per-bgroup
// atomic arrival counter, polled by tid0 only.
#define NCTA 128
#define RTH  256
#define GSZ  16
#define BROWS 8
#define BCOLS 32
// smem (floats): hs pairs [8][512]*2 = 8192, red01 [8][256]*2 = 4096, red2 2048
#define HS_OFF    0
#define RED01_OFF 8192
#define RED2_OFF  12288
#define SMEM_FLOATS 14336
#define RNN_SMEM_BYTES (SMEM_FLOATS * 4)   // 57344 B

__global__ void __launch_bounds__(RTH, 1) rnn_pipe_kernel(
    const float* __restrict__ Whh0, const int* __restrict__ m_hh0,
    const float* __restrict__ Wih1, const int* __restrict__ m_ih1,
    const float* __restrict__ Whh1, const int* __restrict__ m_hh1,
    const float* __restrict__ b_ih1, const float* __restrict__ b_hh1,
    float* __restrict__ out)
{
    extern __shared__ float smem[];
    float* hs    = smem + HS_OFF;      // [8][512] float2 (pairs)
    float* red01 = smem + RED01_OFF;   // [8][256] float2
    float* red2  = smem + RED2_OFF;    // [8][256] float

    const int bg = blockIdx.x >> 4;   // 0..7
    const int hg = blockIdx.x & 15;   // 0..15
    const int b0 = bg * BROWS;
    const int h0 = hg * BCOLS;
    const int tid = threadIdx.x;
    const int col = tid & 31;         // col this thread's k-partials serve
    const int ks  = tid >> 5;         // 0..7, 64-k slice
    const int k0  = ks * 64;

    unsigned* ctr = &g_ctr[bg * 32];

    // ---- permanent register weights: 16 float4 per gemm (64 k) ----
    float4 wr0[16], wr1[16], wr2[16];
    {
        size_t ro = (size_t)(h0 + col) * H_ + k0;
#pragma unroll
        for (int q = 0; q < 16; q++) {
            float4 v; int4 mm;
            v = *(const float4*)&Whh0[ro + 4 * q];
            mm = *(const int4*)&m_hh0[ro + 4 * q];
            wr0[q] = make_float4(v.x * (float)mm.x, v.y * (float)mm.y,
                                 v.z * (float)mm.z, v.w * (float)mm.w);
            v = *(const float4*)&Wih1[ro + 4 * q];
            mm = *(const int4*)&m_ih1[ro + 4 * q];
            wr1[q] = make_float4(v.x * (float)mm.x, v.y * (float)mm.y,
                                 v.z * (float)mm.z, v.w * (float)mm.w);
            v = *(const float4*)&Whh1[ro + 4 * q];
            mm = *(const int4*)&m_hh1[ro + 4 * q];
            wr2[q] = make_float4(v.x * (float)mm.x, v.y * (float)mm.y,
                                 v.z * (float)mm.z, v.w * (float)mm.w);
        }
    }

    // output mapping: thread -> (row tid>>5, col tid&31)
    const int orow = tid >> 5;
    const int ocol = tid & 31;
    const size_t offO = (size_t)(b0 + orow) * H_ + (h0 + ocol);
    float2* my_pack_row0 = &g_pack[0][b0 + orow][h0 + ocol];
    float2* my_pack_row1 = &g_pack[1][b0 + orow][h0 + ocol];
    const float bL1 = __ldg(&b_ih1[h0 + ocol]) + __ldg(&b_hh1[h0 + ocol]);
    float xv = __ldg(&g_buf0[offO]);

    const unsigned hs_b = su32(hs);

    for (int t = 0; t <= S_; ++t) {
        float s0 = 0.f, s1 = 0.f, s2 = 0.f;

        if (t > 0) {
            // ---- wait: counter >= 16*t (tid0 polls, others park) ----
            if (tid == 0) {
                unsigned target = (unsigned)(t * GSZ);
                unsigned c;
                do {
                    asm volatile("ld.acquire.gpu.global.u32 %0, [%1];"
                                 : "=r"(c) : "l"(ctr) : "memory");
                } while (c < target);
            }
            __syncthreads();

            // ---- stage pack[(t-1)&1] rows b0..b0+7 : 32KB, one group ----
            {
                const float2* src = &g_pack[(t - 1) & 1][b0][0];
#pragma unroll
                for (int i = 0; i < 8; i++) {
                    int idx = tid + i * RTH;             // 0..2047 16B chunks
                    cp16(hs_b + (unsigned)idx * 16u, (const char*)src + idx * 16);
                }
            }
            CP_COMMIT();
            CP_WAIT0();
            __syncthreads();

            // ---- fused 3-gemm pass over 8 rows ----
#pragma unroll 2
            for (int r = 0; r < BROWS; r++) {
                const float4* ap4 = (const float4*)(hs + (r * 512 + k0) * 2);
                float2 u0 = make_float2(0.f, 0.f);
                float2 u1 = make_float2(0.f, 0.f);
                float2 u2 = make_float2(0.f, 0.f);
#pragma unroll
                for (int q = 0; q < 16; q++) {
                    float4 d0 = ap4[2 * q];       // cols 4q,4q+1: (y0,y1,y0,y1)
                    float4 d1 = ap4[2 * q + 1];   // cols 4q+2,4q+3
                    float4 w0 = wr0[q], w1 = wr1[q], w2 = wr2[q];
                    fma2(u0, d0.x, d0.z, w0.x, w0.y);
                    fma2(u0, d1.x, d1.z, w0.z, w0.w);
                    fma2(u1, d0.x, d0.z, w1.x, w1.y);
                    fma2(u1, d1.x, d1.z, w1.z, w1.w);
                    fma2(u2, d0.y, d0.w, w2.x, w2.y);
                    fma2(u2, d1.y, d1.w, w2.z, w2.w);
                }
                *(float2*)&red01[(ks * 256 + r * 32 + col) * 2] =
                    make_float2(u0.x + u0.y, u1.x + u1.y);
                red2[ks * 256 + r * 32 + col] = u2.x + u2.y;
            }
            __syncthreads();

            // ---- 8-way k-slice reduction ----
#pragma unroll
            for (int k = 0; k < 8; k++) {
                float2 v = *(const float2*)&red01[(k * 256 + tid) * 2];
                s0 += v.x;
                s1 += v.y;
                s2 += red2[k * 256 + tid];
            }
        }

        float y0v = 0.f, y1v = 0.f;
        if (t < S_) y0v = tanhf(s0 + xv);
        if (t > 0)  y1v = tanhf(s1 + s2 + bL1);

        if (t == S_) {
            out[offO] = y1v;                 // final y1[S-1] straight to output
        } else {
            // publish (y0[t], y1[t-1]) to the ring slot t&1
            float2* dst = (t & 1) ? my_pack_row1 : my_pack_row0;
            *dst = make_float2(y0v, y1v);    // y1v == 0 at t==0 (correct h0)
            if (t + 1 < S_)
                xv = __ldg(&g_buf0[(size_t)(t + 1) * BH_ + offO]);

            // arrive (release orders the pack store)
            __syncthreads();
            if (tid == 0) {
                unsigned old;
                asm volatile("atom.acq_rel.gpu.global.add.u32 %0, [%1], 1;"
                             : "=r"(old) : "l"(ctr) : "memory");
            }
        }
    }
}

// ---------------- launch ----------------
extern "C" void kernel_launch(void* const* d_in, const int* in_sizes, int n_in,
                              void* d_out, int out_size) {
    const float* x       = (const float*)d_in[0];
    const float* W_ih0   = (const float*)d_in[1];
    const float* W_hh0   = (const float*)d_in[2];
    const float* b_ih0   = (const float*)d_in[3];
    const float* b_hh0   = (const float*)d_in[4];
    const float* W_ih1   = (const float*)d_in[5];
    const float* W_hh1   = (const float*)d_in[6];
    const float* b_ih1   = (const float*)d_in[7];
    const float* b_hh1   = (const float*)d_in[8];
    const int*   m_ih0   = (const int*)d_in[9];
    const int*   m_hh0   = (const int*)d_in[10];
    const int*   m_ih1   = (const int*)d_in[11];
    const int*   m_hh1   = (const int*)d_in[12];
    float* out = (float*)d_out;

    static bool attr_set = false;
    if (!attr_set) {
        cudaFuncSetAttribute(rnn_pipe_kernel,
                             cudaFuncAttributeMaxDynamicSharedMemorySize,
                             RNN_SMEM_BYTES);
        attr_set = true;
    }

    init_ctrs_kernel<<<1, 256>>>();

    dim3 pgrid(ROWS_ / TM, H_ / TN);
    proj_kernel<<<pgrid, 256>>>(x, W_ih0, m_ih0, b_ih0, b_hh0, I_);

    rnn_pipe_kernel<<<NCTA, RTH, RNN_SMEM_BYTES>>>(
        W_hh0, m_hh0, W_ih1, m_ih1, W_hh1, m_hh1, b_ih1, b_hh1, out);
}